// round 13
// baseline (speedup 1.0000x reference)
#include <cuda_runtime.h>
#include <math.h>
#include <stdint.h>

// MultiStepUnitaryGCN collapses algebraically to a per-node MLP:
//   h   = relu(cos(sqrt(d)) * (x @ W1^T) + b1)
//   o   = cos(0.5*sqrt(d)) * (h @ W2^T) + b2
//   out = log_softmax(o, axis=1)
// (star-evolution weights are [cos(t*sqrt(d)),0,...]; neighbors unused;
//  nbr_mask arrives as int32 [N,16]).
//
// R12 -> R13: revert the (neutral) staging overlap; repack tiles so each
// thread's fragments for TWO consecutive k-groups are one contiguous uint4:
//   pos(g,lr) = (g>>1)*16 + lr*4 + (g&1)*2   (2 words per (g,lr) pair)
// -> all GEMM A/B fragment fetches become LDS.128 (half the instructions).
// AS=144 (=16 mod 32) makes every 8-lane LDS.128 phase tile the 32 banks
// exactly (starts lq*16+lr*4 = 0,4,...,28): zero conflicts.

#define N_NODES 50000
#define KNBR    16
#define CIN     128
#define CHID    128
#define COUT    64
#define TM      128
#define THREADS 512
#define NTILES  391
#define GRID    148
#define AS      144      // packed tile row stride (words), ≡16 mod 32

// smem words:
//  sW1 [128*144]=18432  sW2 [64*144]=9216  sA [128*144]=18432 (x then h)
//  sC1[128] sC2[128] sB1[128] sB2[64] sR1[512] sR2[512]
#define SMEM_WORDS (18432 + 9216 + 18432 + 128 + 128 + 128 + 64 + 512 + 512)
#define SMEM_BYTES (SMEM_WORDS * 4)

__device__ __forceinline__ uint32_t f2tf(float f) {
    uint32_t u; asm("cvt.rna.tf32.f32 %0, %1;" : "=r"(u) : "f"(f)); return u;
}

__device__ __forceinline__ void mma8(float* d, uint32_t a0, uint32_t a1,
                                     uint32_t a2, uint32_t a3,
                                     uint32_t b0, uint32_t b1) {
    asm volatile(
        "mma.sync.aligned.m16n8k8.row.col.f32.tf32.tf32.f32 "
        "{%0,%1,%2,%3}, {%4,%5,%6,%7}, {%8,%9}, {%0,%1,%2,%3};"
        : "+f"(d[0]), "+f"(d[1]), "+f"(d[2]), "+f"(d[3])
        : "r"(a0), "r"(a1), "r"(a2), "r"(a3), "r"(b0), "r"(b1));
}

__global__ void __launch_bounds__(THREADS, 1)
gcn_mma_kernel(const float* __restrict__ x, const int* __restrict__ mask,
               const float* __restrict__ W1, const float* __restrict__ b1,
               const float* __restrict__ W2, const float* __restrict__ b2,
               float* __restrict__ out)
{
    extern __shared__ uint32_t smem[];
    uint32_t* sW1 = smem;                       // 18432
    uint32_t* sW2 = smem + 18432;               // 9216
    uint32_t* sA  = smem + 27648;               // 18432 (x, then h)
    float*    sC1 = (float*)(smem + 46080);
    float*    sC2 = sC1 + 128;
    float*    sB1 = sC2 + 128;
    float*    sB2 = sB1 + 128;
    float*    sR1 = sB2 + 64;                   // 512: per-row per-wc max
    float*    sR2 = sR1 + 512;                  // 512: per-row per-wc sum

    const int tid  = threadIdx.x;
    const int lane = tid & 31;
    const int warp = tid >> 5;
    const int wr   = warp >> 2;                 // 0..3 row group
    const int wc   = warp & 3;                  // 0..3 col quarter
    const int m0   = wr * 32;
    const int lq   = lane >> 2;                 // 0..7
    const int lr   = lane & 3;                  // 0..3

    // ---- stage W1 packed (once, rna tf32): idx over col x 16k-chunk
    for (int idx = tid; idx < CHID * 8; idx += THREADS) {
        int c = idx >> 3, gq = idx & 7;
        const float* wp = W1 + c * CIN + gq * 16;
        float4 c0 = *(const float4*)(wp);
        float4 c1 = *(const float4*)(wp + 4);
        float4 c2 = *(const float4*)(wp + 8);
        float4 c3 = *(const float4*)(wp + 12);
        uint4* p = (uint4*)(sW1 + c * AS + gq * 16);
        p[0] = make_uint4(f2tf(c0.x), f2tf(c1.x), f2tf(c2.x), f2tf(c3.x));
        p[1] = make_uint4(f2tf(c0.y), f2tf(c1.y), f2tf(c2.y), f2tf(c3.y));
        p[2] = make_uint4(f2tf(c0.z), f2tf(c1.z), f2tf(c2.z), f2tf(c3.z));
        p[3] = make_uint4(f2tf(c0.w), f2tf(c1.w), f2tf(c2.w), f2tf(c3.w));
    }
    // ---- stage W2 packed (once, rna tf32)
    for (int idx = tid; idx < COUT * 8; idx += THREADS) {
        int c = idx >> 3, gq = idx & 7;
        const float* wp = W2 + c * CHID + gq * 16;
        float4 c0 = *(const float4*)(wp);
        float4 c1 = *(const float4*)(wp + 4);
        float4 c2 = *(const float4*)(wp + 8);
        float4 c3 = *(const float4*)(wp + 12);
        uint4* p = (uint4*)(sW2 + c * AS + gq * 16);
        p[0] = make_uint4(f2tf(c0.x), f2tf(c1.x), f2tf(c2.x), f2tf(c3.x));
        p[1] = make_uint4(f2tf(c0.y), f2tf(c1.y), f2tf(c2.y), f2tf(c3.y));
        p[2] = make_uint4(f2tf(c0.z), f2tf(c1.z), f2tf(c2.z), f2tf(c3.z));
        p[3] = make_uint4(f2tf(c0.w), f2tf(c1.w), f2tf(c2.w), f2tf(c3.w));
    }
    if (tid < CHID) sB1[tid] = b1[tid];
    if (tid < COUT) sB2[tid] = b2[tid];

    for (int tile = blockIdx.x; tile < NTILES; tile += GRID) {
        const int row0 = tile * TM;

        // ---- stage x tile packed (raw fp32 bits -> tf32 truncation in HMMA)
        for (int idx = tid; idx < TM * 8; idx += THREADS) {
            int r = idx >> 3, gq = idx & 7;
            float4 c0 = make_float4(0.f, 0.f, 0.f, 0.f), c1 = c0, c2 = c0, c3 = c0;
            if (row0 + r < N_NODES) {
                const float* xp = x + (size_t)(row0 + r) * CIN + gq * 16;
                c0 = *(const float4*)(xp);
                c1 = *(const float4*)(xp + 4);
                c2 = *(const float4*)(xp + 8);
                c3 = *(const float4*)(xp + 12);
            }
            uint4* p = (uint4*)(sA + r * AS + gq * 16);
            p[0] = make_uint4(__float_as_uint(c0.x), __float_as_uint(c1.x),
                              __float_as_uint(c2.x), __float_as_uint(c3.x));
            p[1] = make_uint4(__float_as_uint(c0.y), __float_as_uint(c1.y),
                              __float_as_uint(c2.y), __float_as_uint(c3.y));
            p[2] = make_uint4(__float_as_uint(c0.z), __float_as_uint(c1.z),
                              __float_as_uint(c2.z), __float_as_uint(c3.z));
            p[3] = make_uint4(__float_as_uint(c0.w), __float_as_uint(c1.w),
                              __float_as_uint(c2.w), __float_as_uint(c3.w));
        }
        // ---- per-tile cos factors
        if (tid < TM) {
            int r = row0 + tid;
            float c1 = 0.f, c2 = 0.f;
            if (r < N_NODES) {
                const int4* mp = (const int4*)(mask + (size_t)r * KNBR);
                int4 a = mp[0], b = mp[1], c = mp[2], d4 = mp[3];
                int d = a.x + a.y + a.z + a.w + b.x + b.y + b.z + b.w
                      + c.x + c.y + c.z + c.w + d4.x + d4.y + d4.z + d4.w;
                float sd = sqrtf((float)d);
                c1 = cosf(sd);
                c2 = cosf(0.5f * sd);
            }
            sC1[tid] = c1;
            sC2[tid] = c2;
        }
        __syncthreads();

        // ---- GEMM1: 128x128 = X @ W1^T ; all fragment fetches LDS.128
        float d1[2][4][4];
#pragma unroll
        for (int mt = 0; mt < 2; ++mt)
#pragma unroll
            for (int nt = 0; nt < 4; ++nt)
#pragma unroll
                for (int j = 0; j < 4; ++j) d1[mt][nt][j] = 0.f;

#pragma unroll
        for (int g2 = 0; g2 < 8; ++g2) {
            const int go = g2 * 16 + lr * 4;
            uint4 A0[2], A1[2];
#pragma unroll
            for (int mt = 0; mt < 2; ++mt) {
                int r = m0 + mt * 16 + lq;
                A0[mt] = *(const uint4*)(sA + r * AS + go);
                A1[mt] = *(const uint4*)(sA + (r + 8) * AS + go);
            }
#pragma unroll
            for (int nt = 0; nt < 4; ++nt) {
                int col = wc * 32 + nt * 8 + lq;
                uint4 B = *(const uint4*)(sW1 + col * AS + go);
#pragma unroll
                for (int mt = 0; mt < 2; ++mt) {
                    mma8(d1[mt][nt], A0[mt].x, A1[mt].x, A0[mt].y, A1[mt].y, B.x, B.y);
                    mma8(d1[mt][nt], A0[mt].z, A1[mt].z, A0[mt].w, A1[mt].w, B.z, B.w);
                }
            }
        }
        __syncthreads();   // all warps done reading x from sA

        // ---- epilogue1: h = relu(c1*d + b1) -> sA packed (rna tf32)
        // k=c goes to word (wc*2+(nt>>1))*16 + (lr&1)*8 + (nt&1)*2 + (lr>>1)
#pragma unroll
        for (int mt = 0; mt < 2; ++mt) {
            int r = m0 + mt * 16 + lq;
            float c1a = sC1[r], c1b = sC1[r + 8];
#pragma unroll
            for (int nt = 0; nt < 4; ++nt) {
                int c = wc * 32 + nt * 8 + 2 * lr;
                float bx = sB1[c], by = sB1[c + 1];
                int p0 = (wc * 2 + (nt >> 1)) * 16 + (lr & 1) * 8
                       + (nt & 1) * 2 + (lr >> 1);
                int p1 = p0 + 4;
                sA[r * AS + p0] = f2tf(fmaxf(fmaf(c1a, d1[mt][nt][0], bx), 0.f));
                sA[r * AS + p1] = f2tf(fmaxf(fmaf(c1a, d1[mt][nt][1], by), 0.f));
                sA[(r + 8) * AS + p0] = f2tf(fmaxf(fmaf(c1b, d1[mt][nt][2], bx), 0.f));
                sA[(r + 8) * AS + p1] = f2tf(fmaxf(fmaf(c1b, d1[mt][nt][3], by), 0.f));
            }
        }
        __syncthreads();

        // ---- GEMM2: 128x64 = H @ W2^T ; LDS.128 fetches
        float d2[2][2][4];
#pragma unroll
        for (int mt = 0; mt < 2; ++mt)
#pragma unroll
            for (int nt = 0; nt < 2; ++nt)
#pragma unroll
                for (int j = 0; j < 4; ++j) d2[mt][nt][j] = 0.f;

#pragma unroll
        for (int g2 = 0; g2 < 8; ++g2) {
            const int go = g2 * 16 + lr * 4;
            uint4 A0[2], A1[2];
#pragma unroll
            for (int mt = 0; mt < 2; ++mt) {
                int r = m0 + mt * 16 + lq;
                A0[mt] = *(const uint4*)(sA + r * AS + go);
                A1[mt] = *(const uint4*)(sA + (r + 8) * AS + go);
            }
#pragma unroll
            for (int nt = 0; nt < 2; ++nt) {
                int col = wc * 16 + nt * 8 + lq;
                uint4 B = *(const uint4*)(sW2 + col * AS + go);
#pragma unroll
                for (int mt = 0; mt < 2; ++mt) {
                    mma8(d2[mt][nt], A0[mt].x, A1[mt].x, A0[mt].y, A1[mt].y, B.x, B.y);
                    mma8(d2[mt][nt], A0[mt].z, A1[mt].z, A0[mt].w, A1[mt].w, B.z, B.w);
                }
            }
        }

        // ---- epilogue2: o = c2*d + b2 (regs) ; row-max partials -> sR1
        float o[2][2][4];
        float rmax[2][2] = {{-1e30f, -1e30f}, {-1e30f, -1e30f}};
#pragma unroll
        for (int mt = 0; mt < 2; ++mt) {
            int r = m0 + mt * 16 + lq;
            float c2a = sC2[r], c2b = sC2[r + 8];
#pragma unroll
            for (int nt = 0; nt < 2; ++nt) {
                int c = wc * 16 + nt * 8 + 2 * lr;
                float bx = sB2[c], by = sB2[c + 1];
                o[mt][nt][0] = fmaf(c2a, d2[mt][nt][0], bx);
                o[mt][nt][1] = fmaf(c2a, d2[mt][nt][1], by);
                o[mt][nt][2] = fmaf(c2b, d2[mt][nt][2], bx);
                o[mt][nt][3] = fmaf(c2b, d2[mt][nt][3], by);
                rmax[mt][0] = fmaxf(rmax[mt][0], fmaxf(o[mt][nt][0], o[mt][nt][1]));
                rmax[mt][1] = fmaxf(rmax[mt][1], fmaxf(o[mt][nt][2], o[mt][nt][3]));
            }
        }
#pragma unroll
        for (int mt = 0; mt < 2; ++mt)
#pragma unroll
            for (int i = 0; i < 2; ++i) {
                float m = rmax[mt][i];
                m = fmaxf(m, __shfl_xor_sync(0xffffffffu, m, 1));
                m = fmaxf(m, __shfl_xor_sync(0xffffffffu, m, 2));
                int r = m0 + mt * 16 + i * 8 + lq;
                sR1[r * 4 + wc] = m;
            }
        __syncthreads();

        float gmax[2][2], psum[2][2];
#pragma unroll
        for (int mt = 0; mt < 2; ++mt)
#pragma unroll
            for (int i = 0; i < 2; ++i) {
                int r = m0 + mt * 16 + i * 8 + lq;
                const float4 mv = *(const float4*)(sR1 + r * 4);
                gmax[mt][i] = fmaxf(fmaxf(mv.x, mv.y), fmaxf(mv.z, mv.w));
            }
#pragma unroll
        for (int mt = 0; mt < 2; ++mt) {
            float s0 = 0.f, s1 = 0.f;
#pragma unroll
            for (int nt = 0; nt < 2; ++nt) {
                s0 += expf(o[mt][nt][0] - gmax[mt][0]);
                s0 += expf(o[mt][nt][1] - gmax[mt][0]);
                s1 += expf(o[mt][nt][2] - gmax[mt][1]);
                s1 += expf(o[mt][nt][3] - gmax[mt][1]);
            }
            psum[mt][0] = s0;
            psum[mt][1] = s1;
        }
#pragma unroll
        for (int mt = 0; mt < 2; ++mt)
#pragma unroll
            for (int i = 0; i < 2; ++i) {
                float s = psum[mt][i];
                s += __shfl_xor_sync(0xffffffffu, s, 1);
                s += __shfl_xor_sync(0xffffffffu, s, 2);
                int r = m0 + mt * 16 + i * 8 + lq;
                sR2[r * 4 + wc] = s;
            }
        __syncthreads();

        // ---- lse + store
#pragma unroll
        for (int mt = 0; mt < 2; ++mt)
#pragma unroll
            for (int i = 0; i < 2; ++i) {
                int r = m0 + mt * 16 + i * 8 + lq;
                int grow = row0 + r;
                const float4 sv = *(const float4*)(sR2 + r * 4);
                float lse = gmax[mt][i] + logf(sv.x + sv.y + sv.z + sv.w);
                if (grow < N_NODES) {
                    float* dst = out + (size_t)grow * COUT + wc * 16 + 2 * lr;
#pragma unroll
                    for (int nt = 0; nt < 2; ++nt) {
                        float v0 = o[mt][nt][2 * i]     - lse;
                        float v1 = o[mt][nt][2 * i + 1] - lse;
                        *(float2*)(dst + nt * 8) = make_float2(v0, v1);
                    }
                }
            }
        __syncthreads();   // sR2/sA reads drained before next-tile staging
    }
}

extern "C" void kernel_launch(void* const* d_in, const int* in_sizes, int n_in,
                              void* d_out, int out_size)
{
    const float* x    = (const float*)d_in[0];
    // d_in[1] = neighbors (unused)
    const int*   mask = (const int*)d_in[2];
    const float* W1   = (const float*)d_in[3];
    const float* b1   = (const float*)d_in[4];
    const float* W2   = (const float*)d_in[5];
    const float* b2   = (const float*)d_in[6];
    float*       out  = (float*)d_out;

    cudaFuncSetAttribute(gcn_mma_kernel,
                         cudaFuncAttributeMaxDynamicSharedMemorySize, SMEM_BYTES);

    gcn_mma_kernel<<<GRID, THREADS, SMEM_BYTES>>>(x, mask, W1, b1, W2, b2, out);
}

// round 14
// speedup vs baseline: 1.1712x; 1.1712x over previous
#include <cuda_runtime.h>
#include <math.h>
#include <stdint.h>

// MultiStepUnitaryGCN collapses algebraically to a per-node MLP:
//   h   = relu(cos(sqrt(d)) * (x @ W1^T) + b1)
//   o   = cos(0.5*sqrt(d)) * (h @ W2^T) + b2
//   out = log_softmax(o, axis=1)
// (star-evolution weights [cos(t*sqrt(d)),0,...]; neighbors unused;
//  nbr_mask int32 [N,16]).
//
// R13 -> R14: revert LDS.128 repack (crossbar is byte-bound; R13 regressed).
// Back to R11's validated pair-packed LDS.64 layout (AS=136, conflict-free),
// but the 16 warps are split into TWO independent 8-warp groups, each
// working its own 64-row tile stream with its own sA/sC/sR buffers and
// NAMED barriers (bar.sync 1+g, 256). Groups share one smem copy of W1/W2.
// Group phase bubbles (staging/epilogue/softmax) overlap the other group's
// GEMMs -> latency-bound issue gap closes without any extra smem traffic.

#define N_NODES 50000
#define KNBR    16
#define CIN     128
#define CHID    128
#define COUT    64
#define TM      64       // rows per group-tile
#define THREADS 512
#define NTILES  782      // ceil(50000/64)
#define GRID    148
#define AS      136      // packed tile row stride (words), ≡8 mod 32

// smem words:
//  sW1 17408 | sW2 8704 | sA0 8704 | sA1 8704 |
//  sC1 2*64 | sC2 2*64 | sB1 128 | sB2 64 | sR1 2*256 | sR2 2*256
#define SMEM_WORDS 44992
#define SMEM_BYTES (SMEM_WORDS * 4)

__device__ __forceinline__ uint32_t f2tf(float f) {
    uint32_t u; asm("cvt.rna.tf32.f32 %0, %1;" : "=r"(u) : "f"(f)); return u;
}

__device__ __forceinline__ void mma8(float* d, uint2 aP0, uint2 aP1, uint2 bP) {
    asm volatile(
        "mma.sync.aligned.m16n8k8.row.col.f32.tf32.tf32.f32 "
        "{%0,%1,%2,%3}, {%4,%5,%6,%7}, {%8,%9}, {%0,%1,%2,%3};"
        : "+f"(d[0]), "+f"(d[1]), "+f"(d[2]), "+f"(d[3])
        : "r"(aP0.x), "r"(aP1.x), "r"(aP0.y), "r"(aP1.y),
          "r"(bP.x), "r"(bP.y));
}

__global__ void __launch_bounds__(THREADS, 1)
gcn_mma_kernel(const float* __restrict__ x, const int* __restrict__ mask,
               const float* __restrict__ W1, const float* __restrict__ b1,
               const float* __restrict__ W2, const float* __restrict__ b2,
               float* __restrict__ out)
{
    extern __shared__ uint32_t smem[];
    const int tid   = threadIdx.x;
    const int lane  = tid & 31;
    const int warp  = tid >> 5;
    const int group = warp >> 3;                // 0/1: independent warp-group
    const int gw    = warp & 7;                 // warp id within group
    const int gtid  = tid & 255;                // thread id within group
    const int wr    = gw >> 2;                  // 0..1: 32-row group
    const int wc    = gw & 3;                   // 0..3: col quarter
    const int m0    = wr * 32;
    const int lq    = lane >> 2;                // 0..7
    const int lr    = lane & 3;                 // 0..3

    uint32_t* sW1 = smem;                                   // 17408
    uint32_t* sW2 = smem + 17408;                           // 8704
    uint32_t* sA  = smem + 26112 + group * 8704;            // per-group tile
    float*    sC1 = (float*)(smem + 43520) + group * 64;
    float*    sC2 = (float*)(smem + 43648) + group * 64;
    float*    sB1 = (float*)(smem + 43776);
    float*    sB2 = (float*)(smem + 43904);
    float*    sR1 = (float*)(smem + 43968) + group * 256;   // per-row/wc max
    float*    sR2 = (float*)(smem + 44480) + group * 256;   // per-row/wc sum

#define GBAR() asm volatile("bar.sync %0, 256;" :: "r"(group + 1) : "memory")

    // ---- stage W1/W2 packed (once, rna tf32), whole CTA
    for (int idx = tid; idx < CHID * 16; idx += THREADS) {
        int c = idx >> 4, g = idx & 15;
        float4 v0 = *(const float4*)(W1 + c * CIN + g * 8);
        float4 v1 = *(const float4*)(W1 + c * CIN + g * 8 + 4);
        uint32_t* p = sW1 + c * AS + g * 8;
        *(uint2*)(p + 0) = make_uint2(f2tf(v0.x), f2tf(v1.x));
        *(uint2*)(p + 2) = make_uint2(f2tf(v0.y), f2tf(v1.y));
        *(uint2*)(p + 4) = make_uint2(f2tf(v0.z), f2tf(v1.z));
        *(uint2*)(p + 6) = make_uint2(f2tf(v0.w), f2tf(v1.w));
    }
    for (int idx = tid; idx < COUT * 16; idx += THREADS) {
        int c = idx >> 4, g = idx & 15;
        float4 v0 = *(const float4*)(W2 + c * CHID + g * 8);
        float4 v1 = *(const float4*)(W2 + c * CHID + g * 8 + 4);
        uint32_t* p = sW2 + c * AS + g * 8;
        *(uint2*)(p + 0) = make_uint2(f2tf(v0.x), f2tf(v1.x));
        *(uint2*)(p + 2) = make_uint2(f2tf(v0.y), f2tf(v1.y));
        *(uint2*)(p + 4) = make_uint2(f2tf(v0.z), f2tf(v1.z));
        *(uint2*)(p + 6) = make_uint2(f2tf(v0.w), f2tf(v1.w));
    }
    if (tid < CHID) sB1[tid] = b1[tid];
    if (tid < COUT) sB2[tid] = b2[tid];
    __syncthreads();    // weights visible to both groups; groups now decouple

    for (int tile = blockIdx.x * 2 + group; tile < NTILES; tile += 2 * GRID) {
        const int row0 = tile * TM;

        // ---- stage x tile packed (raw fp32 bits; tf32 truncation in HMMA)
        for (int idx = gtid; idx < TM * 16; idx += 256) {
            int r = idx >> 4, g = idx & 15;
            float4 v0 = make_float4(0.f, 0.f, 0.f, 0.f), v1 = v0;
            if (row0 + r < N_NODES) {
                v0 = *(const float4*)(x + (size_t)(row0 + r) * CIN + g * 8);
                v1 = *(const float4*)(x + (size_t)(row0 + r) * CIN + g * 8 + 4);
            }
            uint32_t* p = sA + r * AS + g * 8;
            *(uint2*)(p + 0) = make_uint2(__float_as_uint(v0.x), __float_as_uint(v1.x));
            *(uint2*)(p + 2) = make_uint2(__float_as_uint(v0.y), __float_as_uint(v1.y));
            *(uint2*)(p + 4) = make_uint2(__float_as_uint(v0.z), __float_as_uint(v1.z));
            *(uint2*)(p + 6) = make_uint2(__float_as_uint(v0.w), __float_as_uint(v1.w));
        }
        if (gtid < TM) {
            int r = row0 + gtid;
            float c1 = 0.f, c2 = 0.f;
            if (r < N_NODES) {
                const int4* mp = (const int4*)(mask + (size_t)r * KNBR);
                int4 a = mp[0], b = mp[1], c = mp[2], d4 = mp[3];
                int d = a.x + a.y + a.z + a.w + b.x + b.y + b.z + b.w
                      + c.x + c.y + c.z + c.w + d4.x + d4.y + d4.z + d4.w;
                float sd = sqrtf((float)d);
                c1 = cosf(sd);
                c2 = cosf(0.5f * sd);
            }
            sC1[gtid] = c1;
            sC2[gtid] = c2;
        }
        GBAR();

        // ---- GEMM1: 64x128 = X @ W1^T ; warp tile 32x32 ; LDS.64 conflict-free
        float d1[2][4][4];
#pragma unroll
        for (int mt = 0; mt < 2; ++mt)
#pragma unroll
            for (int nt = 0; nt < 4; ++nt)
#pragma unroll
                for (int j = 0; j < 4; ++j) d1[mt][nt][j] = 0.f;

#pragma unroll
        for (int g = 0; g < 16; ++g) {
            const int go = g * 8 + lr * 2;
            uint2 a0[2], a1[2];
#pragma unroll
            for (int mt = 0; mt < 2; ++mt) {
                int r = m0 + mt * 16 + lq;
                a0[mt] = *(const uint2*)(sA + r * AS + go);
                a1[mt] = *(const uint2*)(sA + (r + 8) * AS + go);
            }
#pragma unroll
            for (int nt = 0; nt < 4; ++nt) {
                int col = wc * 32 + nt * 8 + lq;
                uint2 bP = *(const uint2*)(sW1 + col * AS + go);
                mma8(d1[0][nt], a0[0], a1[0], bP);
                mma8(d1[1][nt], a0[1], a1[1], bP);
            }
        }
        GBAR();   // group done reading x from sA

        // ---- epilogue1: h = relu(c1*d + b1) -> sA packed (rna tf32)
#pragma unroll
        for (int mt = 0; mt < 2; ++mt) {
            int r = m0 + mt * 16 + lq;
            float c1a = sC1[r], c1b = sC1[r + 8];
#pragma unroll
            for (int nt = 0; nt < 4; ++nt) {
                int c = wc * 32 + nt * 8 + 2 * lr;
                float bx = sB1[c], by = sB1[c + 1];
                int g2 = wc * 4 + nt;
                int p0 = g2 * 8 + ((lr < 2) ? 4 * lr     : 4 * (lr - 2) + 1);
                int p1 = g2 * 8 + ((lr < 2) ? 4 * lr + 2 : 4 * (lr - 2) + 3);
                sA[r * AS + p0] = f2tf(fmaxf(fmaf(c1a, d1[mt][nt][0], bx), 0.f));
                sA[r * AS + p1] = f2tf(fmaxf(fmaf(c1a, d1[mt][nt][1], by), 0.f));
                sA[(r + 8) * AS + p0] = f2tf(fmaxf(fmaf(c1b, d1[mt][nt][2], bx), 0.f));
                sA[(r + 8) * AS + p1] = f2tf(fmaxf(fmaf(c1b, d1[mt][nt][3], by), 0.f));
            }
        }
        GBAR();

        // ---- GEMM2: 64x64 = H @ W2^T ; warp tile 32x16
        float d2[2][2][4];
#pragma unroll
        for (int mt = 0; mt < 2; ++mt)
#pragma unroll
            for (int nt = 0; nt < 2; ++nt)
#pragma unroll
                for (int j = 0; j < 4; ++j) d2[mt][nt][j] = 0.f;

#pragma unroll
        for (int g = 0; g < 16; ++g) {
            const int go = g * 8 + lr * 2;
            uint2 a0[2], a1[2];
#pragma unroll
            for (int mt = 0; mt < 2; ++mt) {
                int r = m0 + mt * 16 + lq;
                a0[mt] = *(const uint2*)(sA + r * AS + go);
                a1[mt] = *(const uint2*)(sA + (r + 8) * AS + go);
            }
#pragma unroll
            for (int nt = 0; nt < 2; ++nt) {
                int col = wc * 16 + nt * 8 + lq;
                uint2 bP = *(const uint2*)(sW2 + col * AS + go);
                mma8(d2[0][nt], a0[0], a1[0], bP);
                mma8(d2[1][nt], a0[1], a1[1], bP);
            }
        }

        // ---- epilogue2: o = c2*d + b2 (regs) ; row-max partials -> sR1
        float o[2][2][4];
        float rmax[2][2] = {{-1e30f, -1e30f}, {-1e30f, -1e30f}};
#pragma unroll
        for (int mt = 0; mt < 2; ++mt) {
            int r = m0 + mt * 16 + lq;
            float c2a = sC2[r], c2b = sC2[r + 8];
#pragma unroll
            for (int nt = 0; nt < 2; ++nt) {
                int c = wc * 16 + nt * 8 + 2 * lr;
                float bx = sB2[c], by = sB2[c + 1];
                o[mt][nt][0] = fmaf(c2a, d2[mt][nt][0], bx);
                o[mt][nt][1] = fmaf(c2a, d2[mt][nt][1], by);
                o[mt][nt][2] = fmaf(c2b, d2[mt][nt][2], bx);
                o[mt][nt][3] = fmaf(c2b, d2[mt][nt][3], by);
                rmax[mt][0] = fmaxf(rmax[mt][0], fmaxf(o[mt][nt][0], o[mt][nt][1]));
                rmax[mt][1] = fmaxf(rmax[mt][1], fmaxf(o[mt][nt][2], o[mt][nt][3]));
            }
        }
#pragma unroll
        for (int mt = 0; mt < 2; ++mt)
#pragma unroll
            for (int i = 0; i < 2; ++i) {
                float m = rmax[mt][i];
                m = fmaxf(m, __shfl_xor_sync(0xffffffffu, m, 1));
                m = fmaxf(m, __shfl_xor_sync(0xffffffffu, m, 2));
                int r = m0 + mt * 16 + i * 8 + lq;
                sR1[r * 4 + wc] = m;
            }
        GBAR();   // sR1 ready; group's sA reads drained

        float gmax[2][2], psum[2][2];
#pragma unroll
        for (int mt = 0; mt < 2; ++mt)
#pragma unroll
            for (int i = 0; i < 2; ++i) {
                int r = m0 + mt * 16 + i * 8 + lq;
                const float4 mv = *(const float4*)(sR1 + r * 4);
                gmax[mt][i] = fmaxf(fmaxf(mv.x, mv.y), fmaxf(mv.z, mv.w));
            }
#pragma unroll
        for (int mt = 0; mt < 2; ++mt) {
            float s0 = 0.f, s1 = 0.f;
#pragma unroll
            for (int nt = 0; nt < 2; ++nt) {
                s0 += expf(o[mt][nt][0] - gmax[mt][0]);
                s0 += expf(o[mt][nt][1] - gmax[mt][0]);
                s1 += expf(o[mt][nt][2] - gmax[mt][1]);
                s1 += expf(o[mt][nt][3] - gmax[mt][1]);
            }
            psum[mt][0] = s0;
            psum[mt][1] = s1;
        }
#pragma unroll
        for (int mt = 0; mt < 2; ++mt)
#pragma unroll
            for (int i = 0; i < 2; ++i) {
                float s = psum[mt][i];
                s += __shfl_xor_sync(0xffffffffu, s, 1);
                s += __shfl_xor_sync(0xffffffffu, s, 2);
                int r = m0 + mt * 16 + i * 8 + lq;
                sR2[r * 4 + wc] = s;
            }
        GBAR();

        // ---- lse + store (registers + sR2 only; next staging can't clash)
#pragma unroll
        for (int mt = 0; mt < 2; ++mt)
#pragma unroll
            for (int i = 0; i < 2; ++i) {
                int r = m0 + mt * 16 + i * 8 + lq;
                int grow = row0 + r;
                const float4 sv = *(const float4*)(sR2 + r * 4);
                float lse = gmax[mt][i] + logf(sv.x + sv.y + sv.z + sv.w);
                if (grow < N_NODES) {
                    float* dst = out + (size_t)grow * COUT + wc * 16 + 2 * lr;
#pragma unroll
                    for (int nt = 0; nt < 2; ++nt) {
                        float v0 = o[mt][nt][2 * i]     - lse;
                        float v1 = o[mt][nt][2 * i + 1] - lse;
                        *(float2*)(dst + nt * 8) = make_float2(v0, v1);
                    }
                }
            }
        GBAR();   // sR2 reads done before next tile's warps touch buffers
    }
#undef GBAR
}

extern "C" void kernel_launch(void* const* d_in, const int* in_sizes, int n_in,
                              void* d_out, int out_size)
{
    const float* x    = (const float*)d_in[0];
    // d_in[1] = neighbors (unused)
    const int*   mask = (const int*)d_in[2];
    const float* W1   = (const float*)d_in[3];
    const float* b1   = (const float*)d_in[4];
    const float* W2   = (const float*)d_in[5];
    const float* b2   = (const float*)d_in[6];
    float*       out  = (float*)d_out;

    cudaFuncSetAttribute(gcn_mma_kernel,
                         cudaFuncAttributeMaxDynamicSharedMemorySize, SMEM_BYTES);

    gcn_mma_kernel<<<GRID, THREADS, SMEM_BYTES>>>(x, mask, W1, b1, W2, b2, out);
}